// round 12
// baseline (speedup 1.0000x reference)
#include <cuda_runtime.h>
#include <cuda_bf16.h>
#include <cstdint>

// Problem shape (fixed): B=2048, D=768, NP=8, P=16384
constexpr int B  = 2048;
constexpr int D  = 768;
constexpr int NP = 8;
constexpr int P  = B * NP;

constexpr float ALPHA = 2.6f;
constexpr float OPT_RANK = 1.0f;
constexpr float SIGMA = 1.8f;
constexpr float SHIFT = 80.0f;   // fixed logsumexp shift / exp threshold

// GEMM tiling: CTA 128x256, 8 warps (2x4), warp tile 64x64, BK=64, 3-stage
constexpr int BM = 128;
constexpr int BN = 256;
constexpr int BK = 64;
constexpr int NT = D / BK;          // 12
constexpr int LDE = 72;             // smem row pitch in elems (144B; ldsm conflict-free)

constexpr int STAGE_A = BM * LDE * 2;        // 18432 B
constexpr int STAGE_B = BN * LDE * 2;        // 36864 B
constexpr int STAGE   = STAGE_A + STAGE_B;   // 55296 B
constexpr int SMEM_DYN = 3 * STAGE;          // 165888 B

// ---- static device scratch ----
__device__ __nv_bfloat16 g_qb[(size_t)B * D];   // 3 MB
__device__ __nv_bfloat16 g_pb[(size_t)P * D];   // 24 MB
__device__ float    g_st[B];
__device__ float    g_sum[B];
__device__ int      g_cnt[B];
__device__ unsigned g_ticket;

// ======================= PTX helpers (sm_80-era only) ===================
__device__ __forceinline__ uint32_t smem_u32(const void* p) {
    uint32_t a;
    asm("{ .reg .u64 t; cvta.to.shared.u64 t, %1; cvt.u32.u64 %0, t; }"
        : "=r"(a) : "l"(p));
    return a;
}
__device__ __forceinline__ void cp16(uint32_t dst, const void* src) {
    asm volatile("cp.async.cg.shared.global [%0], [%1], 16;"
                 :: "r"(dst), "l"(src) : "memory");
}
__device__ __forceinline__ void cp_commit() {
    asm volatile("cp.async.commit_group;" ::: "memory");
}
template <int N>
__device__ __forceinline__ void cp_wait() {
    asm volatile("cp.async.wait_group %0;" :: "n"(N) : "memory");
}
__device__ __forceinline__ void ldsm4(uint32_t* r, uint32_t addr) {
    asm volatile("ldmatrix.sync.aligned.m8n8.x4.shared.b16 {%0,%1,%2,%3}, [%4];"
                 : "=r"(r[0]), "=r"(r[1]), "=r"(r[2]), "=r"(r[3]) : "r"(addr));
}
__device__ __forceinline__ void mma16816(float* c, const uint32_t* a, const uint32_t* b) {
    asm volatile(
        "mma.sync.aligned.m16n8k16.row.col.f32.bf16.bf16.f32 "
        "{%0,%1,%2,%3}, {%4,%5,%6,%7}, {%8,%9}, {%0,%1,%2,%3};"
        : "+f"(c[0]), "+f"(c[1]), "+f"(c[2]), "+f"(c[3])
        : "r"(a[0]), "r"(a[1]), "r"(a[2]), "r"(a[3]), "r"(b[0]), "r"(b[1]));
}

// ======================================================================
// K0: fp32 -> bf16 convert  +  fp32 target-score dot  +  accumulator reset
//     grid = 2048 blocks x 256. Warp 0 of block b computes st[b].
// ======================================================================
__global__ void __launch_bounds__(256) convert_st_kernel(const float* __restrict__ q,
                                                         const float* __restrict__ p) {
    const int tid = threadIdx.x;
    const int gid = blockIdx.x * 256 + tid;
    const int stride = gridDim.x * 256;

    // per-row accumulator reset (one row per block) + ticket reset
    if (tid == 32) g_sum[blockIdx.x] = 0.0f;
    if (tid == 33) g_cnt[blockIdx.x] = 0;
    if (gid == 64) g_ticket = 0u;

    // bulk convert
    const float4* q4 = reinterpret_cast<const float4*>(q);
    const float4* p4 = reinterpret_cast<const float4*>(p);
    __nv_bfloat162* qb2 = reinterpret_cast<__nv_bfloat162*>(g_qb);
    __nv_bfloat162* pb2 = reinterpret_cast<__nv_bfloat162*>(g_pb);
    int nq = (B * D) / 4, np = (P * D) / 4;
    for (int i = gid; i < nq; i += stride) {
        float4 v = q4[i];
        qb2[2 * i]     = __floats2bfloat162_rn(v.x, v.y);
        qb2[2 * i + 1] = __floats2bfloat162_rn(v.z, v.w);
    }
    for (int i = gid; i < np; i += stride) {
        float4 v = p4[i];
        pb2[2 * i]     = __floats2bfloat162_rn(v.x, v.y);
        pb2[2 * i + 1] = __floats2bfloat162_rn(v.z, v.w);
    }

    // warp 0: st[row] = fp32 dot(q[row], p[8*row])
    if (tid < 32) {
        const int row = blockIdx.x;
        const float4* qr = reinterpret_cast<const float4*>(q + (size_t)row * D);
        const float4* pr = reinterpret_cast<const float4*>(p + (size_t)row * NP * D);
        float acc = 0.0f;
        #pragma unroll
        for (int k = tid; k < D / 4; k += 32) {
            float4 a = qr[k], b = pr[k];
            acc += a.x * b.x + a.y * b.y + a.z * b.z + a.w * b.w;
        }
        #pragma unroll
        for (int o = 16; o > 0; o >>= 1) acc += __shfl_xor_sync(0xFFFFFFFFu, acc, o);
        if (tid == 0) g_st[row] = acc;
    }
}

// ======================================================================
// K1: mma.sync bf16 GEMM 128x256 + fused softmax/rank epilogue + finalize
// ======================================================================
__global__ void __launch_bounds__(256, 1) gemm_fused_kernel(float* __restrict__ out) {
    extern __shared__ char dsm[];
    __shared__ float sum_s[BM];
    __shared__ int   cnt_s[BM];
    __shared__ float fred[256];
    __shared__ unsigned s_last;

    const int tid  = threadIdx.x;
    const int warp = tid >> 5;
    const int lane = tid & 31;
    const int wr = warp >> 2;        // 0..1 (row group of 64)
    const int wc = warp & 3;         // 0..3 (col group of 64)
    const int r0 = blockIdx.y * BM;
    const int c0 = blockIdx.x * BN;

    if (tid < BM) { sum_s[tid] = 0.0f; cnt_s[tid] = 0; }

    const uint32_t sb = smem_u32(dsm);

    float acc[4][8][4] = {};           // 128 fp32 accumulators

    // ---- tile loader: A 4 chunks/thread, B 8 chunks/thread (16B each) ----
    auto load_tile = [&](int t, int buf) {
        uint32_t ab = sb + (uint32_t)buf * STAGE;
        uint32_t bb = ab + STAGE_A;
        const __nv_bfloat16* gq = g_qb + (size_t)r0 * D + t * BK;
        const __nv_bfloat16* gp = g_pb + (size_t)c0 * D + t * BK;
        #pragma unroll
        for (int i = 0; i < 4; i++) {                 // A: 1024 chunks
            int idx = i * 256 + tid;
            int row = idx >> 3, q = idx & 7;
            cp16(ab + (uint32_t)(row * LDE + q * 8) * 2, gq + (size_t)row * D + q * 8);
        }
        #pragma unroll
        for (int i = 0; i < 8; i++) {                 // B: 2048 chunks
            int idx = i * 256 + tid;
            int row = idx >> 3, q = idx & 7;
            cp16(bb + (uint32_t)(row * LDE + q * 8) * 2, gp + (size_t)row * D + q * 8);
        }
        cp_commit();
    };

    // ---- compute one K-tile (4 x k16) from a buffer ----
    auto compute = [&](int buf) {
        uint32_t ab = sb + (uint32_t)buf * STAGE;
        uint32_t bb = ab + STAGE_A;
        #pragma unroll
        for (int kk = 0; kk < 4; kk++) {
            uint32_t a[4][4], bf[4][4];
            #pragma unroll
            for (int i = 0; i < 4; i++) {
                int row = wr * 64 + i * 16 + (lane & 15);
                int col = kk * 16 + (lane >> 4) * 8;
                ldsm4(a[i], ab + (uint32_t)(row * LDE + col) * 2);
            }
            #pragma unroll
            for (int j = 0; j < 4; j++) {
                int nrow = wc * 64 + j * 16 + ((lane >> 4) << 3) + (lane & 7);
                int col  = kk * 16 + ((lane >> 3) & 1) * 8;
                ldsm4(bf[j], bb + (uint32_t)(nrow * LDE + col) * 2);
            }
            #pragma unroll
            for (int i = 0; i < 4; i++)
                #pragma unroll
                for (int j = 0; j < 4; j++) {
                    mma16816(acc[i][2 * j],     a[i], &bf[j][0]);
                    mma16816(acc[i][2 * j + 1], a[i], &bf[j][2]);
                }
        }
    };

    // ---- mainloop: 3-stage cp.async pipeline ----
    load_tile(0, 0);
    load_tile(1, 1);
    int cur = 0, nxt = 2;
    #pragma unroll 1
    for (int t = 0; t < NT; t++) {
        if (t + 2 < NT)       { load_tile(t + 2, nxt); cp_wait<2>(); }
        else if (t + 2 == NT) cp_wait<1>();
        else                  cp_wait<0>();
        __syncthreads();
        compute(cur);
        __syncthreads();
        cur = (cur == 2) ? 0 : cur + 1;
        nxt = (nxt == 2) ? 0 : nxt + 1;
    }

    // ---- fused epilogue ----
    const int qrow = lane >> 2;
    float psum[8];
    int   pcnt[8];

    #pragma unroll
    for (int i = 0; i < 4; i++) {
        #pragma unroll
        for (int h = 0; h < 2; h++) {
            int idx = i * 2 + h;
            int grow = r0 + wr * 64 + i * 16 + h * 8 + qrow;
            float st = g_st[grow];
            int tgt = grow * NP;
            float sum = 0.0f;
            int cnt = 0;
            #pragma unroll
            for (int jj = 0; jj < 8; jj++) {
                int jc = c0 + wc * 64 + jj * 8 + (lane & 3) * 2;
                float v0 = acc[i][jj][h * 2 + 0];
                float v1 = acc[i][jj][h * 2 + 1];
                bool g0 = (v0 > st) || (v0 == st && jc < tgt);
                bool g1 = (v1 > st) || (v1 == st && jc + 1 < tgt);
                if (g0 && jc != tgt) cnt++;
                if (g1 && jc + 1 != tgt) cnt++;
                if (v0 > SHIFT) sum += __expf(v0 - SHIFT);
                if (v1 > SHIFT) sum += __expf(v1 - SHIFT);
            }
            psum[idx] = sum;
            pcnt[idx] = cnt;
        }
    }

    #pragma unroll
    for (int idx = 0; idx < 8; idx++) {
        psum[idx] += __shfl_xor_sync(0xFFFFFFFFu, psum[idx], 1);
        psum[idx] += __shfl_xor_sync(0xFFFFFFFFu, psum[idx], 2);
        pcnt[idx] += __shfl_xor_sync(0xFFFFFFFFu, pcnt[idx], 1);
        pcnt[idx] += __shfl_xor_sync(0xFFFFFFFFu, pcnt[idx], 2);
    }
    if ((lane & 3) == 0) {
        #pragma unroll
        for (int idx = 0; idx < 8; idx++) {
            int lrow = wr * 64 + (idx >> 1) * 16 + (idx & 1) * 8 + qrow;
            if (psum[idx] != 0.0f) atomicAdd(&sum_s[lrow], psum[idx]);
            if (pcnt[idx])         atomicAdd(&cnt_s[lrow], pcnt[idx]);
        }
    }
    __syncthreads();
    if (tid < BM) {
        if (sum_s[tid] != 0.0f) atomicAdd(&g_sum[r0 + tid], sum_s[tid]);
        if (cnt_s[tid])         atomicAdd(&g_cnt[r0 + tid], cnt_s[tid]);
    }

    // ---- ticket: last CTA computes the final loss ----
    __threadfence();
    __syncthreads();
    if (tid == 0) {
        unsigned old = atomicAdd(&g_ticket, 1u);
        s_last = (old == gridDim.x * gridDim.y - 1) ? 1u : 0u;
    }
    __syncthreads();
    if (s_last) {
        __threadfence();
        float accf = 0.0f;
        for (int r = tid; r < B; r += 256) {
            float sv = __ldcg(&g_sum[r]);
            int   cv = __ldcg(&g_cnt[r]);
            float rawl = logf(sv) + SHIFT - g_st[r];
            float d = (float)cv - OPT_RANK;
            float w = 1.0f + ALPHA * expf(-(d * d) / (2.0f * SIGMA * SIGMA));
            accf += rawl * w;
        }
        fred[tid] = accf;
        __syncthreads();
        for (int o = 128; o > 0; o >>= 1) {
            if (tid < o) fred[tid] += fred[tid + o];
            __syncthreads();
        }
        if (tid == 0) out[0] = fred[0] * (1.0f / (float)B);
    }
}

// ======================================================================
extern "C" void kernel_launch(void* const* d_in, const int* in_sizes, int n_in,
                              void* d_out, int out_size) {
    const float* q = (const float*)d_in[0];
    const float* p = (const float*)d_in[1];
    float* out = (float*)d_out;

    cudaFuncSetAttribute(gemm_fused_kernel,
                         cudaFuncAttributeMaxDynamicSharedMemorySize, SMEM_DYN);

    convert_st_kernel<<<B, 256>>>(q, p);
    dim3 grid(P / BN, B / BM);               // 64 x 16 = 1024 CTAs
    gemm_fused_kernel<<<grid, 256, SMEM_DYN>>>(out);
}

// round 17
// speedup vs baseline: 1.0439x; 1.0439x over previous
#include <cuda_runtime.h>
#include <cuda_bf16.h>
#include <cstdint>

// Problem shape (fixed): B=2048, D=768, NP=8, P=16384
constexpr int B  = 2048;
constexpr int D  = 768;
constexpr int NP = 8;
constexpr int P  = B * NP;

constexpr float ALPHA = 2.6f;
constexpr float OPT_RANK = 1.0f;
constexpr float SIGMA = 1.8f;
constexpr float SHIFT = 80.0f;   // fixed logsumexp shift / exp threshold

// GEMM tiling: CTA 256x128, 16 warps (4x4), warp tile 64x32, BK=64, 3-stage
constexpr int BM = 256;
constexpr int BN = 128;
constexpr int BK = 64;
constexpr int NT = D / BK;          // 12
constexpr int LDE = 72;             // smem row pitch in elems (144B; ldsm conflict-free)

constexpr int STAGE_A = BM * LDE * 2;        // 36864 B
constexpr int STAGE_B = BN * LDE * 2;        // 18432 B
constexpr int STAGE   = STAGE_A + STAGE_B;   // 55296 B
constexpr int SMEM_DYN = 3 * STAGE;          // 165888 B

// ---- static device scratch ----
__device__ __nv_bfloat16 g_qb[(size_t)B * D];   // 3 MB
__device__ __nv_bfloat16 g_pb[(size_t)P * D];   // 24 MB
__device__ float    g_st[B];
__device__ float    g_sum[B];
__device__ int      g_cnt[B];
__device__ unsigned g_ticket;

// ======================= PTX helpers (sm_80-era only) ===================
__device__ __forceinline__ uint32_t smem_u32(const void* p) {
    uint32_t a;
    asm("{ .reg .u64 t; cvta.to.shared.u64 t, %1; cvt.u32.u64 %0, t; }"
        : "=r"(a) : "l"(p));
    return a;
}
__device__ __forceinline__ void cp16(uint32_t dst, const void* src) {
    asm volatile("cp.async.cg.shared.global [%0], [%1], 16;"
                 :: "r"(dst), "l"(src) : "memory");
}
__device__ __forceinline__ void cp_commit() {
    asm volatile("cp.async.commit_group;" ::: "memory");
}
template <int N>
__device__ __forceinline__ void cp_wait() {
    asm volatile("cp.async.wait_group %0;" :: "n"(N) : "memory");
}
__device__ __forceinline__ void ldsm4(uint32_t* r, uint32_t addr) {
    asm volatile("ldmatrix.sync.aligned.m8n8.x4.shared.b16 {%0,%1,%2,%3}, [%4];"
                 : "=r"(r[0]), "=r"(r[1]), "=r"(r[2]), "=r"(r[3]) : "r"(addr));
}
__device__ __forceinline__ void mma16816(float* c, const uint32_t* a, const uint32_t* b) {
    asm volatile(
        "mma.sync.aligned.m16n8k16.row.col.f32.bf16.bf16.f32 "
        "{%0,%1,%2,%3}, {%4,%5,%6,%7}, {%8,%9}, {%0,%1,%2,%3};"
        : "+f"(c[0]), "+f"(c[1]), "+f"(c[2]), "+f"(c[3])
        : "r"(a[0]), "r"(a[1]), "r"(a[2]), "r"(a[3]), "r"(b[0]), "r"(b[1]));
}

// ======================================================================
// K0: fp32 -> bf16 convert  +  fp32 target-score dot  +  accumulator reset
//     grid = 2048 blocks x 256. Warp 0 of block b computes st[b].
// ======================================================================
__global__ void __launch_bounds__(256) convert_st_kernel(const float* __restrict__ q,
                                                         const float* __restrict__ p) {
    const int tid = threadIdx.x;
    const int gid = blockIdx.x * 256 + tid;
    const int stride = gridDim.x * 256;

    if (tid == 32) g_sum[blockIdx.x] = 0.0f;
    if (tid == 33) g_cnt[blockIdx.x] = 0;
    if (gid == 64) g_ticket = 0u;

    const float4* q4 = reinterpret_cast<const float4*>(q);
    const float4* p4 = reinterpret_cast<const float4*>(p);
    __nv_bfloat162* qb2 = reinterpret_cast<__nv_bfloat162*>(g_qb);
    __nv_bfloat162* pb2 = reinterpret_cast<__nv_bfloat162*>(g_pb);
    int nq = (B * D) / 4, np = (P * D) / 4;
    for (int i = gid; i < nq; i += stride) {
        float4 v = q4[i];
        qb2[2 * i]     = __floats2bfloat162_rn(v.x, v.y);
        qb2[2 * i + 1] = __floats2bfloat162_rn(v.z, v.w);
    }
    for (int i = gid; i < np; i += stride) {
        float4 v = p4[i];
        pb2[2 * i]     = __floats2bfloat162_rn(v.x, v.y);
        pb2[2 * i + 1] = __floats2bfloat162_rn(v.z, v.w);
    }

    if (tid < 32) {
        const int row = blockIdx.x;
        const float4* qr = reinterpret_cast<const float4*>(q + (size_t)row * D);
        const float4* pr = reinterpret_cast<const float4*>(p + (size_t)row * NP * D);
        float acc = 0.0f;
        #pragma unroll
        for (int k = tid; k < D / 4; k += 32) {
            float4 a = qr[k], b = pr[k];
            acc += a.x * b.x + a.y * b.y + a.z * b.z + a.w * b.w;
        }
        #pragma unroll
        for (int o = 16; o > 0; o >>= 1) acc += __shfl_xor_sync(0xFFFFFFFFu, acc, o);
        if (tid == 0) g_st[row] = acc;
    }
}

// ======================================================================
// K1: mma.sync bf16 GEMM 256x128 (16 warps) + fused epilogue + finalize
// ======================================================================
__global__ void __launch_bounds__(512, 1) gemm_fused_kernel(float* __restrict__ out) {
    extern __shared__ char dsm[];
    __shared__ float sum_s[BM];
    __shared__ int   cnt_s[BM];
    __shared__ float fred[512];
    __shared__ unsigned s_last;

    const int tid  = threadIdx.x;
    const int warp = tid >> 5;
    const int lane = tid & 31;
    const int wr = warp >> 2;        // 0..3 (row group of 64)
    const int wc = warp & 3;         // 0..3 (col group of 32)
    const int r0 = blockIdx.y * BM;
    const int c0 = blockIdx.x * BN;

    if (tid < BM) { sum_s[tid] = 0.0f; cnt_s[tid] = 0; }

    const uint32_t sb = smem_u32(dsm);

    float acc[4][4][4] = {};           // 64 fp32 accumulators (64x32 warp tile)

    // ---- tile loader: A 4 chunks/thread, B 2 chunks/thread (16B each) ----
    auto load_tile = [&](int t, int buf) {
        uint32_t ab = sb + (uint32_t)buf * STAGE;
        uint32_t bb = ab + STAGE_A;
        const __nv_bfloat16* gq = g_qb + (size_t)r0 * D + t * BK;
        const __nv_bfloat16* gp = g_pb + (size_t)c0 * D + t * BK;
        #pragma unroll
        for (int i = 0; i < 4; i++) {                 // A: 2048 chunks
            int idx = i * 512 + tid;
            int row = idx >> 3, q = idx & 7;
            cp16(ab + (uint32_t)(row * LDE + q * 8) * 2, gq + (size_t)row * D + q * 8);
        }
        #pragma unroll
        for (int i = 0; i < 2; i++) {                 // B: 1024 chunks
            int idx = i * 512 + tid;
            int row = idx >> 3, q = idx & 7;
            cp16(bb + (uint32_t)(row * LDE + q * 8) * 2, gp + (size_t)row * D + q * 8);
        }
        cp_commit();
    };

    // ---- compute one K-tile (4 x k16), ldsm/mma interleaved ----
    auto compute = [&](int buf) {
        uint32_t ab = sb + (uint32_t)buf * STAGE;
        uint32_t bb = ab + STAGE_A;
        #pragma unroll
        for (int kk = 0; kk < 4; kk++) {
            uint32_t bfr[2][4];
            #pragma unroll
            for (int j = 0; j < 2; j++) {
                int nrow = wc * 32 + j * 16 + ((lane >> 4) << 3) + (lane & 7);
                int col  = kk * 16 + ((lane >> 3) & 1) * 8;
                ldsm4(bfr[j], bb + (uint32_t)(nrow * LDE + col) * 2);
            }
            uint32_t a[4][4];
            {
                int row = wr * 64 + 0 * 16 + (lane & 15);
                int col = kk * 16 + (lane >> 4) * 8;
                ldsm4(a[0], ab + (uint32_t)(row * LDE + col) * 2);
            }
            #pragma unroll
            for (int i = 0; i < 4; i++) {
                if (i < 3) {
                    int row = wr * 64 + (i + 1) * 16 + (lane & 15);
                    int col = kk * 16 + (lane >> 4) * 8;
                    ldsm4(a[i + 1], ab + (uint32_t)(row * LDE + col) * 2);
                }
                #pragma unroll
                for (int j = 0; j < 2; j++) {
                    mma16816(acc[i][2 * j],     a[i], &bfr[j][0]);
                    mma16816(acc[i][2 * j + 1], a[i], &bfr[j][2]);
                }
            }
        }
    };

    // ---- mainloop: 3-stage cp.async pipeline ----
    load_tile(0, 0);
    load_tile(1, 1);
    int cur = 0, nxt = 2;
    #pragma unroll 1
    for (int t = 0; t < NT; t++) {
        if (t + 2 < NT)       { load_tile(t + 2, nxt); cp_wait<2>(); }
        else if (t + 2 == NT) cp_wait<1>();
        else                  cp_wait<0>();
        __syncthreads();
        compute(cur);
        __syncthreads();
        cur = (cur == 2) ? 0 : cur + 1;
        nxt = (nxt == 2) ? 0 : nxt + 1;
    }

    // ---- fused epilogue ----
    const int qrow = lane >> 2;
    float psum[8];
    int   pcnt[8];

    #pragma unroll
    for (int i = 0; i < 4; i++) {
        #pragma unroll
        for (int h = 0; h < 2; h++) {
            int idx = i * 2 + h;
            int grow = r0 + wr * 64 + i * 16 + h * 8 + qrow;
            float st = g_st[grow];
            int tgt = grow * NP;
            float sum = 0.0f;
            int cnt = 0;
            #pragma unroll
            for (int jj = 0; jj < 4; jj++) {
                int jc = c0 + wc * 32 + jj * 8 + (lane & 3) * 2;
                float v0 = acc[i][jj][h * 2 + 0];
                float v1 = acc[i][jj][h * 2 + 1];
                bool g0 = (v0 > st) || (v0 == st && jc < tgt);
                bool g1 = (v1 > st) || (v1 == st && jc + 1 < tgt);
                if (g0 && jc != tgt) cnt++;
                if (g1 && jc + 1 != tgt) cnt++;
                if (v0 > SHIFT) sum += __expf(v0 - SHIFT);
                if (v1 > SHIFT) sum += __expf(v1 - SHIFT);
            }
            psum[idx] = sum;
            pcnt[idx] = cnt;
        }
    }

    #pragma unroll
    for (int idx = 0; idx < 8; idx++) {
        psum[idx] += __shfl_xor_sync(0xFFFFFFFFu, psum[idx], 1);
        psum[idx] += __shfl_xor_sync(0xFFFFFFFFu, psum[idx], 2);
        pcnt[idx] += __shfl_xor_sync(0xFFFFFFFFu, pcnt[idx], 1);
        pcnt[idx] += __shfl_xor_sync(0xFFFFFFFFu, pcnt[idx], 2);
    }
    if ((lane & 3) == 0) {
        #pragma unroll
        for (int idx = 0; idx < 8; idx++) {
            int lrow = wr * 64 + (idx >> 1) * 16 + (idx & 1) * 8 + qrow;
            if (psum[idx] != 0.0f) atomicAdd(&sum_s[lrow], psum[idx]);
            if (pcnt[idx])         atomicAdd(&cnt_s[lrow], pcnt[idx]);
        }
    }
    __syncthreads();
    if (tid < BM) {
        if (sum_s[tid] != 0.0f) atomicAdd(&g_sum[r0 + tid], sum_s[tid]);
        if (cnt_s[tid])         atomicAdd(&g_cnt[r0 + tid], cnt_s[tid]);
    }

    // ---- ticket: last CTA computes the final loss ----
    __threadfence();
    __syncthreads();
    if (tid == 0) {
        unsigned old = atomicAdd(&g_ticket, 1u);
        s_last = (old == gridDim.x * gridDim.y - 1) ? 1u : 0u;
    }
    __syncthreads();
    if (s_last) {
        __threadfence();
        float accf = 0.0f;
        for (int r = tid; r < B; r += 512) {
            float sv = __ldcg(&g_sum[r]);
            int   cv = __ldcg(&g_cnt[r]);
            float rawl = logf(sv) + SHIFT - g_st[r];
            float d = (float)cv - OPT_RANK;
            float w = 1.0f + ALPHA * expf(-(d * d) / (2.0f * SIGMA * SIGMA));
            accf += rawl * w;
        }
        fred[tid] = accf;
        __syncthreads();
        for (int o = 256; o > 0; o >>= 1) {
            if (tid < o) fred[tid] += fred[tid + o];
            __syncthreads();
        }
        if (tid == 0) out[0] = fred[0] * (1.0f / (float)B);
    }
}

// ======================================================================
extern "C" void kernel_launch(void* const* d_in, const int* in_sizes, int n_in,
                              void* d_out, int out_size) {
    const float* q = (const float*)d_in[0];
    const float* p = (const float*)d_in[1];
    float* out = (float*)d_out;

    cudaFuncSetAttribute(gemm_fused_kernel,
                         cudaFuncAttributeMaxDynamicSharedMemorySize, SMEM_DYN);

    convert_st_kernel<<<B, 256>>>(q, p);
    dim3 grid(P / BN, B / BM);               // 128 x 8 = 1024 CTAs
    gemm_fused_kernel<<<grid, 512, SMEM_DYN>>>(out);
}